// round 8
// baseline (speedup 1.0000x reference)
#include <cuda_runtime.h>
#include <math.h>

#define NPFS  4
#define NF    512
#define NP    256
#define BATCH 128
#define NMAT  (BATCH * NPFS)            // 512 matrices
#define NTHR  512
#define NW    (NTHR / 32)               // 16 warps

// padded, 16B-aligned row bases for the lower triangle
__device__ __host__ __forceinline__ unsigned rowb(int r) {
    return ((unsigned)((r * (r - 1)) / 2 + 6 * r)) & ~3u;
}
#define L_ELEMS 34176                    // >= rowb(255) + 260, mult of 4

// Scratch (__device__ globals — allocations forbidden)
__device__ float g_sign[NMAT];
__device__ float g_logabs[NMAT];

__device__ __forceinline__ void wred(float& bv, int& bi) {
    #pragma unroll
    for (int off = 16; off; off >>= 1) {
        float ov = __shfl_down_sync(0xffffffffu, bv, off);
        int   oi = __shfl_down_sync(0xffffffffu, bi, off);
        if (ov > bv || (ov == bv && oi < bi)) { bv = ov; bi = oi; }
    }
}

// ---------------------------------------------------------------------------
// Kernel: one CTA per matrix. Lower triangle (padded rows) in smem.
// Parlett-Reid with partial pivoting, TWO elimination steps fused into ONE
// trailing rank-4 pass (8 rows per warp). Antisymmetrization fused into the
// gather. Pass: peeled extraction iteration + unguarded main + guarded tail.
// ---------------------------------------------------------------------------
__global__ __launch_bounds__(NTHR, 1)
void pf_kernel(const float* __restrict__ F, const int* __restrict__ idx) {
    extern __shared__ float sm[];
    float* L     = sm;                  // [L_ELEMS]
    float* tau1  = sm + L_ELEMS;        // [NP]
    float* v1    = tau1 + NP;           // [NP]
    float* tau2  = v1 + NP;             // [NP]
    float* v2    = tau2 + NP;           // [NP]
    float* tau1p = v2 + NP;             // [NP]  swap-b-permuted tau1
    float* v1p   = tau1p + NP;          // [NP]
    float* colA  = v1p + NP;            // [NP]  current column k   (updated)
    float* colB  = colA + NP;           // [NP]  current column k+1 (updated)
    float* colBr = colB + NP;           // [NP]  raw column k+3 (pre-update-1)

    __shared__ int   s_idx[NP];
    __shared__ float s_rv[NW];
    __shared__ int   s_ri[NW];

    const int tid  = threadIdx.x;
    const int lane = tid & 31;
    const int wid  = tid >> 5;
    const int m    = blockIdx.x;
    const int b    = m >> 2;
    const int p    = m & 3;

    if (tid < NP) s_idx[tid] = idx[b * NP + tid];
    __syncthreads();

    // ---- gather (warp per row), antisym fused, + col cache + pivot scan ----
    {
        float bv = -1.f; int bi = NP;
        const float* Fp = F + ((size_t)p << 18);
        for (int r = wid; r < NP; r += NW) {
            const int ir = s_idx[r];
            const float* rowp = Fp + ((size_t)ir << 9);
            unsigned base = rowb(r);
            for (int c = lane; c < r; c += 32) {
                const int ic = s_idx[c];
                float val = 0.5f * (__ldg(&rowp[ic]) - __ldg(&Fp[((size_t)ic << 9) + ir]));
                L[base + c] = val;
                if (c == 0) {
                    colA[r] = val;
                    float a = fabsf(val);
                    if (a > bv || (a == bv && r < bi)) { bv = a; bi = r; }
                }
                if (c == 1) colB[r] = val;
            }
        }
        wred(bv, bi);
        if (lane == 0) { s_rv[wid] = bv; s_ri[wid] = bi; }
    }
    __syncthreads();

    float sign = 1.f, logabs = 0.f;   // live in thread 0

    for (int k = 0; k < NP; k += 4) {
        const int p1 = k + 1;
        const int k2 = k + 2;
        const int k3 = k + 3;
        const int k4 = k + 4;
        const int k5 = k + 5;

        // ---- phase A: reduce pivot-a candidates (16-lane butterfly) ----
        float pv = s_rv[lane & (NW - 1)];
        int   pi = s_ri[lane & (NW - 1)];
        #pragma unroll
        for (int off = NW / 2; off; off >>= 1) {
            float ov = __shfl_xor_sync(0xffffffffu, pv, off);
            int   oi = __shfl_xor_sync(0xffffffffu, pi, off);
            if (ov > pv || (ov == pv && oi < pi)) { pv = ov; pi = oi; }
        }
        const int   kp1  = pi;                 // pivot-a row in (k, NP)
        const float piv1 = -colA[kp1];         // post-swap A[k][k+1]
        if (tid == 0) {
            if (kp1 != p1)  sign = -sign;
            if (piv1 < 0.f) sign = -sign;
            logabs += logf(fabsf(piv1));
        }

        // ---- phase B: tau1/v1 fill + live half of swap-a ----
        if (tid >= k2 && tid < NP) {
            const int t = tid;
            const float rp = 1.0f / piv1;
            float ta = (t == kp1 ? colA[p1] : colA[t]) * rp;
            float vv;
            if (kp1 != p1) {
                if (t < kp1) {
                    vv = -L[rowb(kp1) + t];
                    L[rowb(kp1) + t] = -colB[t];
                } else if (t == kp1) {
                    vv = -colB[kp1];
                } else {
                    vv = L[rowb(t) + kp1];
                    L[rowb(t) + kp1] = colB[t];
                }
            } else {
                vv = colB[t];
            }
            tau1[t] = ta;
            v1[t]   = vv;
        }
        __syncthreads();

        // ---- phase C: updated columns k2,k3 (O(n)) + raw col k3 + pivot-b scan ----
        {
            float bv = -1.f; int bi = NP;
            if (tid >= k3 && tid < NP) {
                const int t = tid;
                float2 raw = *(const float2*)&L[rowb(t) + k2];
                const float t1 = tau1[t], w1 = v1[t];
                const float t1k2 = tau1[k2], v1k2 = v1[k2];
                const float t1k3 = tau1[k3], v1k3 = v1[k3];
                float ca = raw.x + w1 * t1k2 - t1 * v1k2;   // A'[t][k2]
                float cb = raw.y + w1 * t1k3 - t1 * v1k3;   // A'[t][k3]
                colA[t]  = ca;
                colB[t]  = cb;
                colBr[t] = raw.y;                            // raw A_a[t][k3]
                bv = fabsf(ca); bi = t;
            }
            wred(bv, bi);
            if (lane == 0) { s_rv[wid] = bv; s_ri[wid] = bi; }
        }
        __syncthreads();

        // ---- phase D: pivot-b reduce; tau2/v2 fill + swap-b (raw writes);
        //      permuted tau1p/v1p ----
        pv = s_rv[lane & (NW - 1)];
        pi = s_ri[lane & (NW - 1)];
        #pragma unroll
        for (int off = NW / 2; off; off >>= 1) {
            float ov = __shfl_xor_sync(0xffffffffu, pv, off);
            int   oi = __shfl_xor_sync(0xffffffffu, pi, off);
            if (ov > pv || (ov == pv && oi < pi)) { pv = ov; pi = oi; }
        }
        const int   kp2  = pi;                 // pivot-b row in (k2, NP)
        const float piv2 = -colA[kp2];         // post-swap A'[k2][k3]
        if (tid == 0) {
            if (kp2 != k3)  sign = -sign;
            if (piv2 < 0.f) sign = -sign;
            logabs += logf(fabsf(piv2));
        }
        if (tid >= k4 && tid < NP) {
            const int t = tid;
            const float rp2 = 1.0f / piv2;
            float ta = (t == kp2 ? colA[k3] : colA[t]) * rp2;
            float vv;
            if (kp2 != k3) {
                if (t < kp2) {
                    vv = -(L[rowb(kp2) + t] + v1[kp2] * tau1[t] - tau1[kp2] * v1[t]);
                    L[rowb(kp2) + t] = -colBr[t];            // raw swap write
                } else if (t == kp2) {
                    vv = -colB[kp2];                         // -A'[kp2][k3]
                } else {
                    vv = L[rowb(t) + kp2] + v1[t] * tau1[kp2] - tau1[t] * v1[kp2];
                    L[rowb(t) + kp2] = colBr[t];             // raw swap write
                }
            } else {
                vv = colB[t];
            }
            tau2[t] = ta;
            v2[t]   = vv;
            tau1p[t] = (t == kp2) ? tau1[k3] : tau1[t];      // P-permuted step-1 vectors
            v1p[t]   = (t == kp2) ? v1[k3]   : v1[t];
        }
        __syncthreads();

        // ---- phase E: ONE rank-4 trailing pass, 8 rows per warp ----
        if (k4 < NP) {
            float bv = -1.f; int bi = NP;
            const int cstart = k4;   // k % 4 == 0 -> 16B aligned
            for (int pr = wid; ; pr += 4 * NW) {
                const int r0 = k5 + 2 * pr;
                if (r0 >= NP) break;

                int      rr[8];
                unsigned bb[8];
                int      ee[8];
                float    tt[8], ww[8], uu[8], zz[8];
                rr[0] = r0;      rr[1] = r0 + 1;
                rr[2] = r0 + 32; rr[3] = r0 + 33;
                rr[4] = r0 + 64; rr[5] = r0 + 65;
                rr[6] = r0 + 96; rr[7] = r0 + 97;
                int emax = 0, emin = 0x7fffffff;
                #pragma unroll
                for (int i = 0; i < 8; i++) {
                    const bool ok = rr[i] < NP;
                    bb[i] = ok ? rowb(rr[i]) : 0u;
                    ee[i] = ok ? ((rr[i] + 3) & ~3) : 0;
                    tt[i] = ok ? tau1p[rr[i]] : 0.f;
                    ww[i] = ok ? v1p[rr[i]]   : 0.f;
                    uu[i] = ok ? tau2[rr[i]]  : 0.f;
                    zz[i] = ok ? v2[rr[i]]    : 0.f;
                    if (ee[i] > emax) emax = ee[i];
                    if (ee[i] < emin) emin = ee[i];
                }

                #define ROW_BODY(I, CC, T1C, W1C, T2C, W2C)                              \
                {                                                                        \
                    float4 x = *(const float4*)&L[bb[I] + (CC)];                         \
                    x.x += ww[I] * T1C.x - tt[I] * W1C.x + zz[I] * T2C.x - uu[I] * W2C.x;\
                    x.y += ww[I] * T1C.y - tt[I] * W1C.y + zz[I] * T2C.y - uu[I] * W2C.y;\
                    x.z += ww[I] * T1C.z - tt[I] * W1C.z + zz[I] * T2C.z - uu[I] * W2C.z;\
                    x.w += ww[I] * T1C.w - tt[I] * W1C.w + zz[I] * T2C.w - uu[I] * W2C.w;\
                    *(float4*)&L[bb[I] + (CC)] = x;                                      \
                }

                // peeled first iteration: guards + extraction (lane 0 has cc==cstart)
                {
                    const int cc = cstart + 4 * lane;
                    if (cc < emax) {
                        const float4 t1c = *(const float4*)&tau1p[cc];
                        const float4 w1c = *(const float4*)&v1p[cc];
                        const float4 t2c = *(const float4*)&tau2[cc];
                        const float4 w2c = *(const float4*)&v2[cc];
                        #pragma unroll
                        for (int i = 0; i < 8; i++) {
                            if (cc < ee[i]) {
                                float4 x = *(const float4*)&L[bb[i] + cc];
                                x.x += ww[i] * t1c.x - tt[i] * w1c.x + zz[i] * t2c.x - uu[i] * w2c.x;
                                x.y += ww[i] * t1c.y - tt[i] * w1c.y + zz[i] * t2c.y - uu[i] * w2c.y;
                                x.z += ww[i] * t1c.z - tt[i] * w1c.z + zz[i] * t2c.z - uu[i] * w2c.z;
                                x.w += ww[i] * t1c.w - tt[i] * w1c.w + zz[i] * t2c.w - uu[i] * w2c.w;
                                *(float4*)&L[bb[i] + cc] = x;
                                if (cc == cstart) {
                                    colA[rr[i]] = x.x; colB[rr[i]] = x.y;
                                    float a_ = fabsf(x.x);
                                    if (a_ > bv || (a_ == bv && rr[i] < bi)) { bv = a_; bi = rr[i]; }
                                }
                            }
                        }
                    }
                }

                // unguarded main loop: every lane's cc < emin for all 8 rows
                int base = cstart + 128;
                for (; base + 127 < emin; base += 128) {
                    const int cc = base + 4 * lane;
                    const float4 t1c = *(const float4*)&tau1p[cc];
                    const float4 w1c = *(const float4*)&v1p[cc];
                    const float4 t2c = *(const float4*)&tau2[cc];
                    const float4 w2c = *(const float4*)&v2[cc];
                    ROW_BODY(0, cc, t1c, w1c, t2c, w2c)
                    ROW_BODY(1, cc, t1c, w1c, t2c, w2c)
                    ROW_BODY(2, cc, t1c, w1c, t2c, w2c)
                    ROW_BODY(3, cc, t1c, w1c, t2c, w2c)
                    ROW_BODY(4, cc, t1c, w1c, t2c, w2c)
                    ROW_BODY(5, cc, t1c, w1c, t2c, w2c)
                    ROW_BODY(6, cc, t1c, w1c, t2c, w2c)
                    ROW_BODY(7, cc, t1c, w1c, t2c, w2c)
                }

                // guarded epilogue
                for (; base < emax; base += 128) {
                    const int cc = base + 4 * lane;
                    if (cc < emax) {
                        const float4 t1c = *(const float4*)&tau1p[cc];
                        const float4 w1c = *(const float4*)&v1p[cc];
                        const float4 t2c = *(const float4*)&tau2[cc];
                        const float4 w2c = *(const float4*)&v2[cc];
                        #pragma unroll
                        for (int i = 0; i < 8; i++) {
                            if (cc < ee[i]) ROW_BODY(i, cc, t1c, w1c, t2c, w2c)
                        }
                    }
                }
                #undef ROW_BODY
            }
            wred(bv, bi);
            if (lane == 0) { s_rv[wid] = bv; s_ri[wid] = bi; }
        }
        __syncthreads();
    }

    if (tid == 0) { g_sign[m] = sign; g_logabs[m] = logabs; }
}

// ---------------------------------------------------------------------------
// signed logsumexp over the 4 pfaffians per batch element
// ---------------------------------------------------------------------------
__global__ void combine_kernel(float* __restrict__ out) {
    int b = threadIdx.x;
    if (b < BATCH) {
        float la[NPFS], sg[NPFS];
        float mx = -INFINITY;
        #pragma unroll
        for (int p = 0; p < NPFS; p++) {
            la[p] = g_logabs[b * NPFS + p];
            sg[p] = g_sign[b * NPFS + p];
            mx = fmaxf(mx, la[p]);
        }
        float val = 0.f;
        #pragma unroll
        for (int p = 0; p < NPFS; p++)
            val += sg[p] * expf(la[p] - mx);
        out[b]         = (val > 0.f) ? 1.f : ((val < 0.f) ? -1.f : 0.f);
        out[BATCH + b] = mx + logf(fabsf(val));
    }
}

// ---------------------------------------------------------------------------
extern "C" void kernel_launch(void* const* d_in, const int* in_sizes, int n_in,
                              void* d_out, int out_size) {
    const float* F   = (const float*)d_in[0];   // (4, 512, 512) fp32
    const int*   idx = (const int*)  d_in[1];   // (128, 256) int32
    float*       out = (float*)d_out;           // (2, 128) fp32

    const size_t shmem = (size_t)(L_ELEMS + 9 * NP) * sizeof(float); // ~142.5 KB
    cudaFuncSetAttribute(pf_kernel, cudaFuncAttributeMaxDynamicSharedMemorySize,
                         (int)shmem);

    pf_kernel<<<NMAT, NTHR, shmem>>>(F, idx);
    combine_kernel<<<1, 128>>>(out);
}

// round 9
// speedup vs baseline: 1.0042x; 1.0042x over previous
#include <cuda_runtime.h>
#include <math.h>

#define NPFS  4
#define NF    512
#define NP    256
#define BATCH 128
#define NMAT  (BATCH * NPFS)            // 512 matrices
#define NTHR  512
#define NW    (NTHR / 32)               // 16 warps

// padded, 16B-aligned row bases for the lower triangle
__device__ __host__ __forceinline__ unsigned rowb(int r) {
    return ((unsigned)((r * (r - 1)) / 2 + 6 * r)) & ~3u;
}
#define L_ELEMS 34176                    // >= rowb(255) + 260, mult of 4

// Scratch (__device__ globals — allocations forbidden)
__device__ float g_sign[NMAT];
__device__ float g_logabs[NMAT];

__device__ __forceinline__ void wred(float& bv, int& bi) {
    #pragma unroll
    for (int off = 16; off; off >>= 1) {
        float ov = __shfl_down_sync(0xffffffffu, bv, off);
        int   oi = __shfl_down_sync(0xffffffffu, bi, off);
        if (ov > bv || (ov == bv && oi < bi)) { bv = ov; bi = oi; }
    }
}

// ---------------------------------------------------------------------------
// Kernel: one CTA per matrix. Lower triangle (padded rows) in smem.
// Parlett-Reid with partial pivoting, TWO elimination steps fused into ONE
// trailing rank-4 pass (4 rows per warp). Antisymmetrization fused into the
// gather. Pass: peeled extraction iteration + unguarded main (all-valid
// groups only) + guarded tail.
// ---------------------------------------------------------------------------
__global__ __launch_bounds__(NTHR, 1)
void pf_kernel(const float* __restrict__ F, const int* __restrict__ idx) {
    extern __shared__ float sm[];
    float* L     = sm;                  // [L_ELEMS]
    float* tau1  = sm + L_ELEMS;        // [NP]
    float* v1    = tau1 + NP;           // [NP]
    float* tau2  = v1 + NP;             // [NP]
    float* v2    = tau2 + NP;           // [NP]
    float* tau1p = v2 + NP;             // [NP]  swap-b-permuted tau1
    float* v1p   = tau1p + NP;          // [NP]
    float* colA  = v1p + NP;            // [NP]  current column k   (updated)
    float* colB  = colA + NP;           // [NP]  current column k+1 (updated)
    float* colBr = colB + NP;           // [NP]  raw column k+3 (pre-update-1)

    __shared__ int   s_idx[NP];
    __shared__ float s_rv[NW];
    __shared__ int   s_ri[NW];

    const int tid  = threadIdx.x;
    const int lane = tid & 31;
    const int wid  = tid >> 5;
    const int m    = blockIdx.x;
    const int b    = m >> 2;
    const int p    = m & 3;

    if (tid < NP) s_idx[tid] = idx[b * NP + tid];
    __syncthreads();

    // ---- gather (warp per row), antisym fused, + col cache + pivot scan ----
    {
        float bv = -1.f; int bi = NP;
        const float* Fp = F + ((size_t)p << 18);
        for (int r = wid; r < NP; r += NW) {
            const int ir = s_idx[r];
            const float* rowp = Fp + ((size_t)ir << 9);
            unsigned base = rowb(r);
            for (int c = lane; c < r; c += 32) {
                const int ic = s_idx[c];
                float val = 0.5f * (__ldg(&rowp[ic]) - __ldg(&Fp[((size_t)ic << 9) + ir]));
                L[base + c] = val;
                if (c == 0) {
                    colA[r] = val;
                    float a = fabsf(val);
                    if (a > bv || (a == bv && r < bi)) { bv = a; bi = r; }
                }
                if (c == 1) colB[r] = val;
            }
        }
        wred(bv, bi);
        if (lane == 0) { s_rv[wid] = bv; s_ri[wid] = bi; }
    }
    __syncthreads();

    float sign = 1.f, logabs = 0.f;   // live in thread 0

    for (int k = 0; k < NP; k += 4) {
        const int p1 = k + 1;
        const int k2 = k + 2;
        const int k3 = k + 3;
        const int k4 = k + 4;
        const int k5 = k + 5;

        // ---- phase A: reduce pivot-a candidates (16-lane butterfly) ----
        float pv = s_rv[lane & (NW - 1)];
        int   pi = s_ri[lane & (NW - 1)];
        #pragma unroll
        for (int off = NW / 2; off; off >>= 1) {
            float ov = __shfl_xor_sync(0xffffffffu, pv, off);
            int   oi = __shfl_xor_sync(0xffffffffu, pi, off);
            if (ov > pv || (ov == pv && oi < pi)) { pv = ov; pi = oi; }
        }
        const int   kp1  = pi;                 // pivot-a row in (k, NP)
        const float piv1 = -colA[kp1];         // post-swap A[k][k+1]
        if (tid == 0) {
            if (kp1 != p1)  sign = -sign;
            if (piv1 < 0.f) sign = -sign;
            logabs += logf(fabsf(piv1));
        }

        // ---- phase B: tau1/v1 fill + live half of swap-a ----
        if (tid >= k2 && tid < NP) {
            const int t = tid;
            const float rp = 1.0f / piv1;
            float ta = (t == kp1 ? colA[p1] : colA[t]) * rp;
            float vv;
            if (kp1 != p1) {
                if (t < kp1) {
                    vv = -L[rowb(kp1) + t];
                    L[rowb(kp1) + t] = -colB[t];
                } else if (t == kp1) {
                    vv = -colB[kp1];
                } else {
                    vv = L[rowb(t) + kp1];
                    L[rowb(t) + kp1] = colB[t];
                }
            } else {
                vv = colB[t];
            }
            tau1[t] = ta;
            v1[t]   = vv;
        }
        __syncthreads();

        // ---- phase C: updated columns k2,k3 (O(n)) + raw col k3 + pivot-b scan ----
        {
            float bv = -1.f; int bi = NP;
            if (tid >= k3 && tid < NP) {
                const int t = tid;
                float2 raw = *(const float2*)&L[rowb(t) + k2];
                const float t1 = tau1[t], w1 = v1[t];
                const float t1k2 = tau1[k2], v1k2 = v1[k2];
                const float t1k3 = tau1[k3], v1k3 = v1[k3];
                float ca = raw.x + w1 * t1k2 - t1 * v1k2;   // A'[t][k2]
                float cb = raw.y + w1 * t1k3 - t1 * v1k3;   // A'[t][k3]
                colA[t]  = ca;
                colB[t]  = cb;
                colBr[t] = raw.y;                            // raw A_a[t][k3]
                bv = fabsf(ca); bi = t;
            }
            wred(bv, bi);
            if (lane == 0) { s_rv[wid] = bv; s_ri[wid] = bi; }
        }
        __syncthreads();

        // ---- phase D: pivot-b reduce; tau2/v2 fill + swap-b (raw writes);
        //      permuted tau1p/v1p ----
        pv = s_rv[lane & (NW - 1)];
        pi = s_ri[lane & (NW - 1)];
        #pragma unroll
        for (int off = NW / 2; off; off >>= 1) {
            float ov = __shfl_xor_sync(0xffffffffu, pv, off);
            int   oi = __shfl_xor_sync(0xffffffffu, pi, off);
            if (ov > pv || (ov == pv && oi < pi)) { pv = ov; pi = oi; }
        }
        const int   kp2  = pi;                 // pivot-b row in (k2, NP)
        const float piv2 = -colA[kp2];         // post-swap A'[k2][k3]
        if (tid == 0) {
            if (kp2 != k3)  sign = -sign;
            if (piv2 < 0.f) sign = -sign;
            logabs += logf(fabsf(piv2));
        }
        if (tid >= k4 && tid < NP) {
            const int t = tid;
            const float rp2 = 1.0f / piv2;
            float ta = (t == kp2 ? colA[k3] : colA[t]) * rp2;
            float vv;
            if (kp2 != k3) {
                if (t < kp2) {
                    vv = -(L[rowb(kp2) + t] + v1[kp2] * tau1[t] - tau1[kp2] * v1[t]);
                    L[rowb(kp2) + t] = -colBr[t];            // raw swap write
                } else if (t == kp2) {
                    vv = -colB[kp2];                         // -A'[kp2][k3]
                } else {
                    vv = L[rowb(t) + kp2] + v1[t] * tau1[kp2] - tau1[t] * v1[kp2];
                    L[rowb(t) + kp2] = colBr[t];             // raw swap write
                }
            } else {
                vv = colB[t];
            }
            tau2[t] = ta;
            v2[t]   = vv;
            tau1p[t] = (t == kp2) ? tau1[k3] : tau1[t];      // P-permuted step-1 vectors
            v1p[t]   = (t == kp2) ? v1[k3]   : v1[t];
        }
        __syncthreads();

        // ---- phase E: ONE rank-4 trailing pass, 4 rows per warp,
        //      peel (extraction) + unguarded main + guarded tail ----
        if (k4 < NP) {
            float bv = -1.f; int bi = NP;
            const int cstart = k4;   // k % 4 == 0 -> 16B aligned
            for (int pr = wid; ; pr += 2 * NW) {
                const int r0 = k5 + 2 * pr;
                if (r0 >= NP) break;
                const int r1 = r0 + 1;
                const int r2 = r0 + 32;
                const int r3 = r0 + 33;
                const bool ok1 = r1 < NP, ok2 = r2 < NP, ok3 = r3 < NP;

                const unsigned b0 = rowb(r0);
                const unsigned b1 = ok1 ? rowb(r1) : 0u;
                const unsigned b2 = ok2 ? rowb(r2) : 0u;
                const unsigned b3 = ok3 ? rowb(r3) : 0u;
                const int e0 = (r0 + 3) & ~3;
                const int e1 = ok1 ? ((r1 + 3) & ~3) : 0;
                const int e2 = ok2 ? ((r2 + 3) & ~3) : 0;
                const int e3 = ok3 ? ((r3 + 3) & ~3) : 0;
                int emax = e0;
                if (e1 > emax) emax = e1;
                if (e2 > emax) emax = e2;
                if (e3 > emax) emax = e3;

                const float t0 = tau1p[r0], w0 = v1p[r0];
                const float u0 = tau2[r0],  z0 = v2[r0];
                const float t1r = ok1 ? tau1p[r1] : 0.f, w1r = ok1 ? v1p[r1] : 0.f;
                const float u1r = ok1 ? tau2[r1]  : 0.f, z1r = ok1 ? v2[r1]  : 0.f;
                const float t2r = ok2 ? tau1p[r2] : 0.f, w2r = ok2 ? v1p[r2] : 0.f;
                const float u2r = ok2 ? tau2[r2]  : 0.f, z2r = ok2 ? v2[r2]  : 0.f;
                const float t3r = ok3 ? tau1p[r3] : 0.f, w3r = ok3 ? v1p[r3] : 0.f;
                const float u3r = ok3 ? tau2[r3]  : 0.f, z3r = ok3 ? v2[r3]  : 0.f;

                #define ROW_BODY(BX, CC, TR, WR, UR, ZR)                                 \
                {                                                                        \
                    float4 x = *(const float4*)&L[BX + (CC)];                            \
                    x.x += WR * t1c.x - TR * w1c.x + ZR * t2c.x - UR * w2c.x;            \
                    x.y += WR * t1c.y - TR * w1c.y + ZR * t2c.y - UR * w2c.y;            \
                    x.z += WR * t1c.z - TR * w1c.z + ZR * t2c.z - UR * w2c.z;            \
                    x.w += WR * t1c.w - TR * w1c.w + ZR * t2c.w - UR * w2c.w;            \
                    *(float4*)&L[BX + (CC)] = x;                                         \
                }
                #define ROW_EXTR(BX, EX, CC, TR, WR, UR, ZR, RX)                         \
                if ((CC) < EX) {                                                         \
                    float4 x = *(const float4*)&L[BX + (CC)];                            \
                    x.x += WR * t1c.x - TR * w1c.x + ZR * t2c.x - UR * w2c.x;            \
                    x.y += WR * t1c.y - TR * w1c.y + ZR * t2c.y - UR * w2c.y;            \
                    x.z += WR * t1c.z - TR * w1c.z + ZR * t2c.z - UR * w2c.z;            \
                    x.w += WR * t1c.w - TR * w1c.w + ZR * t2c.w - UR * w2c.w;            \
                    *(float4*)&L[BX + (CC)] = x;                                         \
                    if ((CC) == cstart) {                                                \
                        colA[RX] = x.x; colB[RX] = x.y;                                  \
                        float a_ = fabsf(x.x);                                           \
                        if (a_ > bv || (a_ == bv && (RX) < bi)) { bv = a_; bi = RX; }    \
                    }                                                                    \
                }

                // peeled first iteration: guards + extraction
                {
                    const int cc = cstart + 4 * lane;
                    if (cc < emax) {
                        const float4 t1c = *(const float4*)&tau1p[cc];
                        const float4 w1c = *(const float4*)&v1p[cc];
                        const float4 t2c = *(const float4*)&tau2[cc];
                        const float4 w2c = *(const float4*)&v2[cc];
                        ROW_EXTR(b0, e0, cc, t0,  w0,  u0,  z0,  r0)
                        ROW_EXTR(b1, e1, cc, t1r, w1r, u1r, z1r, r1)
                        ROW_EXTR(b2, e2, cc, t2r, w2r, u2r, z2r, r2)
                        ROW_EXTR(b3, e3, cc, t3r, w3r, u3r, z3r, r3)
                    }
                }

                int base = cstart + 128;
                if (ok3) {
                    // unguarded main: all 4 rows valid; e0 is the smallest extent
                    for (; base + 127 < e0; base += 128) {
                        const int cc = base + 4 * lane;
                        const float4 t1c = *(const float4*)&tau1p[cc];
                        const float4 w1c = *(const float4*)&v1p[cc];
                        const float4 t2c = *(const float4*)&tau2[cc];
                        const float4 w2c = *(const float4*)&v2[cc];
                        ROW_BODY(b0, cc, t0,  w0,  u0,  z0)
                        ROW_BODY(b1, cc, t1r, w1r, u1r, z1r)
                        ROW_BODY(b2, cc, t2r, w2r, u2r, z2r)
                        ROW_BODY(b3, cc, t3r, w3r, u3r, z3r)
                    }
                }
                // guarded tail
                for (; base < emax; base += 128) {
                    const int cc = base + 4 * lane;
                    if (cc < emax) {
                        const float4 t1c = *(const float4*)&tau1p[cc];
                        const float4 w1c = *(const float4*)&v1p[cc];
                        const float4 t2c = *(const float4*)&tau2[cc];
                        const float4 w2c = *(const float4*)&v2[cc];
                        if (cc < e0) ROW_BODY(b0, cc, t0,  w0,  u0,  z0)
                        if (cc < e1) ROW_BODY(b1, cc, t1r, w1r, u1r, z1r)
                        if (cc < e2) ROW_BODY(b2, cc, t2r, w2r, u2r, z2r)
                        if (cc < e3) ROW_BODY(b3, cc, t3r, w3r, u3r, z3r)
                    }
                }
                #undef ROW_BODY
                #undef ROW_EXTR
            }
            wred(bv, bi);
            if (lane == 0) { s_rv[wid] = bv; s_ri[wid] = bi; }
        }
        __syncthreads();
    }

    if (tid == 0) { g_sign[m] = sign; g_logabs[m] = logabs; }
}

// ---------------------------------------------------------------------------
// signed logsumexp over the 4 pfaffians per batch element
// ---------------------------------------------------------------------------
__global__ void combine_kernel(float* __restrict__ out) {
    int b = threadIdx.x;
    if (b < BATCH) {
        float la[NPFS], sg[NPFS];
        float mx = -INFINITY;
        #pragma unroll
        for (int p = 0; p < NPFS; p++) {
            la[p] = g_logabs[b * NPFS + p];
            sg[p] = g_sign[b * NPFS + p];
            mx = fmaxf(mx, la[p]);
        }
        float val = 0.f;
        #pragma unroll
        for (int p = 0; p < NPFS; p++)
            val += sg[p] * expf(la[p] - mx);
        out[b]         = (val > 0.f) ? 1.f : ((val < 0.f) ? -1.f : 0.f);
        out[BATCH + b] = mx + logf(fabsf(val));
    }
}

// ---------------------------------------------------------------------------
extern "C" void kernel_launch(void* const* d_in, const int* in_sizes, int n_in,
                              void* d_out, int out_size) {
    const float* F   = (const float*)d_in[0];   // (4, 512, 512) fp32
    const int*   idx = (const int*)  d_in[1];   // (128, 256) int32
    float*       out = (float*)d_out;           // (2, 128) fp32

    const size_t shmem = (size_t)(L_ELEMS + 9 * NP) * sizeof(float); // ~142.5 KB
    cudaFuncSetAttribute(pf_kernel, cudaFuncAttributeMaxDynamicSharedMemorySize,
                         (int)shmem);

    pf_kernel<<<NMAT, NTHR, shmem>>>(F, idx);
    combine_kernel<<<1, 128>>>(out);
}